// round 9
// baseline (speedup 1.0000x reference)
#include <cuda_runtime.h>
#include <cuda_bf16.h>
#include <math.h>

#define BDIM 512
#define DDIM 512
#define CDIM 100000
#define SCALE_F 64.0f
#define MARGIN_F 0.35f

#define TILE_N 128
#define NT 782                         // ceil(100000/128)
#define C_PAD (NT * TILE_N)            // padded W rows (zero-filled)
#define NPART (NT * 4)                 // per-row partials (4 warp-columns per tile)
#define GRIDX 37                       // 37*4 = 148 CTAs = 1 wave

#define NSTAGE 4
#define AQ_STRIDE 528                  // A smem row stride bytes (512 + 16)
#define BQ_STRIDE 80                   // B smem row stride bytes (64 + 16)
#define A_SMEM_BYTES (128 * AQ_STRIDE)            // 67584
#define B_STAGE_BYTES (128 * BQ_STRIDE)           // 10240
#define SMEM_DYN (A_SMEM_BYTES + NSTAGE * B_STAGE_BYTES)  // 108544

// ---------------- device scratch ----------------
__device__ uint4  g_xq4[BDIM * 32];                 // x quantized int8 (packed)
__device__ float  g_xn[BDIM * DDIM];                // normalized x fp32 (for cosgt)
__device__ float  g_sx[BDIM];                       // x row scales
__device__ uint4  g_wq4[(size_t)C_PAD * 32];        // W quantized int8 (~51 MB)
__device__ float  g_sw[C_PAD];                      // W row scales (0 on padding)
__device__ float  g_pm[BDIM * NPART];
__device__ float  g_ps[BDIM * NPART];
__device__ float  g_cosgt[BDIM];
__device__ float  g_nll[BDIM];
__device__ int    g_is64;

// ---------------- helpers ----------------
__device__ __forceinline__ unsigned smem_u32(const void* p) {
    unsigned a;
    asm("{ .reg .u64 t; cvta.to.shared.u64 t, %1; cvt.u32.u64 %0, t; }" : "=r"(a) : "l"(p));
    return a;
}
#define CP_ASYNC16(d, s) asm volatile("cp.async.cg.shared.global [%0], [%1], 16;" :: "r"(d), "l"(s) : "memory")
#define CP_COMMIT()  asm volatile("cp.async.commit_group;" ::: "memory")
#define CP_WAIT2()   asm volatile("cp.async.wait_group 2;" ::: "memory")

__device__ __forceinline__ unsigned pack_s8(float a, float b, float c, float d, float inv_s) {
    int q0 = __float2int_rn(a * inv_s) & 0xFF;
    int q1 = __float2int_rn(b * inv_s) & 0xFF;
    int q2 = __float2int_rn(c * inv_s) & 0xFF;
    int q3 = __float2int_rn(d * inv_s);
    return (unsigned)(q0 | (q1 << 8) | (q2 << 16) | (q3 << 24));
}

// frag load, one k32 step (byte offset ksB within 64B chunk rows)
__device__ __forceinline__ void load_frags8(
    unsigned sbA, unsigned bB, int aRow, int aColB, int bRow, int bColB,
    int ksB, unsigned (*a)[4], unsigned (*bf)[2])
{
    #pragma unroll
    for (int i = 0; i < 2; i++) {
        unsigned addr = sbA + (aRow + i * 16) * AQ_STRIDE + ksB + aColB;
        asm volatile("ldmatrix.sync.aligned.m8n8.x4.shared.b16 {%0,%1,%2,%3}, [%4];"
                     : "=r"(a[i][0]), "=r"(a[i][1]), "=r"(a[i][2]), "=r"(a[i][3])
                     : "r"(addr));
    }
    #pragma unroll
    for (int j2 = 0; j2 < 2; j2++) {
        unsigned addr = bB + (bRow + j2 * 16) * BQ_STRIDE + ksB + bColB;
        unsigned r0, r1, r2, r3;
        asm volatile("ldmatrix.sync.aligned.m8n8.x4.shared.b16 {%0,%1,%2,%3}, [%4];"
                     : "=r"(r0), "=r"(r1), "=r"(r2), "=r"(r3) : "r"(addr));
        bf[j2 * 2 + 0][0] = r0; bf[j2 * 2 + 0][1] = r1;
        bf[j2 * 2 + 1][0] = r2; bf[j2 * 2 + 1][1] = r3;
    }
}

// ---------------- small kernels ----------------
__global__ void detect_gt_kernel(const int* __restrict__ graw) {
    __shared__ int any_nz;
    if (threadIdx.x == 0) any_nz = 0;
    __syncthreads();
    if ((threadIdx.x & 1) && graw[threadIdx.x] != 0) any_nz = 1;
    __syncthreads();
    if (threadIdx.x == 0) g_is64 = any_nz ? 0 : 1;
}

__global__ void __launch_bounds__(128) norm_x_kernel(const float* __restrict__ x) {
    int b = blockIdx.x, tid = threadIdx.x;
    float4 v = ((const float4*)(x + (size_t)b * DDIM))[tid];
    float ss = v.x*v.x + v.y*v.y + v.z*v.z + v.w*v.w;
    #pragma unroll
    for (int o = 16; o; o >>= 1) ss += __shfl_xor_sync(0xffffffffu, ss, o);
    __shared__ float sm[4], sm2[4];
    if ((tid & 31) == 0) sm[tid >> 5] = ss;
    __syncthreads();
    float tot = sm[0] + sm[1] + sm[2] + sm[3];
    float r = 1.0f / fmaxf(sqrtf(tot), 1e-12f);
    float4 n = make_float4(v.x*r, v.y*r, v.z*r, v.w*r);
    ((float4*)(g_xn + (size_t)b * DDIM))[tid] = n;
    float mx = fmaxf(fmaxf(fabsf(n.x), fabsf(n.y)), fmaxf(fabsf(n.z), fabsf(n.w)));
    #pragma unroll
    for (int o = 16; o; o >>= 1) mx = fmaxf(mx, __shfl_xor_sync(0xffffffffu, mx, o));
    if ((tid & 31) == 0) sm2[tid >> 5] = mx;
    __syncthreads();
    mx = fmaxf(fmaxf(sm2[0], sm2[1]), fmaxf(sm2[2], sm2[3]));
    mx = fmaxf(mx, 1e-30f);
    float inv_s = 127.0f / mx;
    ((unsigned*)g_xq4)[b * 128 + tid] = pack_s8(n.x, n.y, n.z, n.w, inv_s);
    if (tid == 0) g_sx[b] = mx / 127.0f;
}

__global__ void __launch_bounds__(128) norm_w_kernel(const float* __restrict__ wt) {
    int c = blockIdx.x, tid = threadIdx.x;
    if (c >= CDIM) {   // zero padding rows (masked in epilogue)
        ((unsigned*)g_wq4)[(size_t)c * 128 + tid] = 0u;
        if (tid == 0) g_sw[c] = 0.0f;
        return;
    }
    float4 v = ((const float4*)(wt + (size_t)c * DDIM))[tid];
    float ss = v.x*v.x + v.y*v.y + v.z*v.z + v.w*v.w;
    #pragma unroll
    for (int o = 16; o; o >>= 1) ss += __shfl_xor_sync(0xffffffffu, ss, o);
    __shared__ float sm[4], sm2[4];
    if ((tid & 31) == 0) sm[tid >> 5] = ss;
    __syncthreads();
    float tot = sm[0] + sm[1] + sm[2] + sm[3];
    float r = 1.0f / fmaxf(sqrtf(tot), 1e-12f);
    float4 n = make_float4(v.x*r, v.y*r, v.z*r, v.w*r);
    float mx = fmaxf(fmaxf(fabsf(n.x), fabsf(n.y)), fmaxf(fabsf(n.z), fabsf(n.w)));
    #pragma unroll
    for (int o = 16; o; o >>= 1) mx = fmaxf(mx, __shfl_xor_sync(0xffffffffu, mx, o));
    if ((tid & 31) == 0) sm2[tid >> 5] = mx;
    __syncthreads();
    mx = fmaxf(fmaxf(sm2[0], sm2[1]), fmaxf(sm2[2], sm2[3]));
    mx = fmaxf(mx, 1e-30f);
    float inv_s = 127.0f / mx;
    ((unsigned*)g_wq4)[(size_t)c * 128 + tid] = pack_s8(n.x, n.y, n.z, n.w, inv_s);
    if (tid == 0) g_sw[c] = mx / 127.0f;
}

__global__ void __launch_bounds__(128) cosgt_kernel(const void* __restrict__ gt,
                                                    const float* __restrict__ wt) {
    int b = blockIdx.x, tid = threadIdx.x;
    long long c = g_is64 ? ((const long long*)gt)[b] : (long long)((const int*)gt)[b];
    float4 w  = ((const float4*)(wt + (size_t)c * DDIM))[tid];
    float4 xn = ((const float4*)(g_xn + (size_t)b * DDIM))[tid];
    float ss = w.x*w.x + w.y*w.y + w.z*w.z + w.w*w.w;
    float dp = w.x*xn.x + w.y*xn.y + w.z*xn.z + w.w*xn.w;
    #pragma unroll
    for (int o = 16; o; o >>= 1) {
        ss += __shfl_xor_sync(0xffffffffu, ss, o);
        dp += __shfl_xor_sync(0xffffffffu, dp, o);
    }
    __shared__ float sms[4], smd[4];
    if ((tid & 31) == 0) { sms[tid >> 5] = ss; smd[tid >> 5] = dp; }
    __syncthreads();
    if (tid == 0) {
        float tss = sms[0] + sms[1] + sms[2] + sms[3];
        float tdp = smd[0] + smd[1] + smd[2] + smd[3];
        g_cosgt[b] = tdp / fmaxf(sqrtf(tss), 1e-12f);
    }
}

// ---------------- IMMA GEMM + fused softmax partials ----------------
// grid (37, 4), 512 threads, 16 warps (4m x 4n), warp tile 32x32, s8 k32 MMA.
__global__ void __launch_bounds__(512, 1) gemm_softmax_kernel() {
    extern __shared__ char smem[];
    unsigned sbA = smem_u32(smem);
    unsigned sbB = sbA + A_SMEM_BYTES;

    int tid  = threadIdx.x;
    int lane = tid & 31;
    int warp = tid >> 5;
    int wm = warp >> 2;       // 0..3
    int wn = warp & 3;        // 0..3
    int m0 = blockIdx.y * 128;
    int bx = blockIdx.x;

    const char* wq = (const char*)g_wq4;
    const char* xq = (const char*)g_xq4;

    int seg = tid & 3;        // 16B segment within 64B chunk-row
    int lrow = tid >> 2;      // row 0..127
    int ntiles = (NT - bx + GRIDX - 1) / GRIDX;
    int nchunks = ntiles * 8;

    // ---- issue B chunks 0..2 into stages 0..2 (1 x 16B per thread) ----
    #pragma unroll
    for (int c0 = 0; c0 < 3; c0++) {
        const char* src = wq + (size_t)(bx * TILE_N + lrow) * 512 + c0 * 64 + seg * 16;
        CP_ASYNC16(sbB + c0 * B_STAGE_BYTES + lrow * BQ_STRIDE + seg * 16, src);
        CP_COMMIT();
    }

    // ---- stage A[128 x 512B] into SMEM (once) ----
    #pragma unroll
    for (int it = 0; it < 8; it++) {
        int idx = it * 512 + tid;
        int r = idx >> 5, s = idx & 31;
        uint4 v = *(const uint4*)(xq + (size_t)(m0 + r) * 512 + s * 16);
        *(uint4*)(smem + r * AQ_STRIDE + s * 16) = v;
    }

    int g4 = lane >> 2, t4 = lane & 3;
    int aRow  = wm * 32 + (lane & 15);
    int aColB = (lane >> 4) << 4;                       // byte offset
    int bRow  = wn * 32 + (lane & 7) + ((lane >> 4) << 3);
    int bColB = ((lane >> 3) & 1) << 4;                 // byte offset

    // row dequant factors (invariant across tiles)
    float fxv[4];
    #pragma unroll
    for (int i = 0; i < 2; i++)
        #pragma unroll
        for (int h = 0; h < 2; h++)
            fxv[i * 2 + h] = SCALE_F * g_sx[m0 + wm * 32 + i * 16 + h * 8 + g4];

    int c = 0;   // global chunk index
    #pragma unroll 1
    for (int t = 0; t < ntiles; t++) {
        int nt = bx + t * GRIDX;
        int acc[2][4][4];
        #pragma unroll
        for (int i = 0; i < 2; i++)
            #pragma unroll
            for (int j = 0; j < 4; j++)
                #pragma unroll
                for (int e = 0; e < 4; e++) acc[i][j][e] = 0;

        #pragma unroll 1
        for (int ck = 0; ck < 8; ck++, c++) {
            CP_WAIT2();                 // chunk c resident
            __syncthreads();            // stage (c+3)&3 fully consumed by all warps

            // issue chunk c+3 into stage (c+3)&3 (may cross tile boundary)
            {
                int cn = c + 3;
                if (cn < nchunks) {
                    int nt2 = bx + (cn >> 3) * GRIDX;
                    int ck2 = cn & 7;
                    const char* src = wq + (size_t)(nt2 * TILE_N + lrow) * 512
                                      + ck2 * 64 + seg * 16;
                    CP_ASYNC16(sbB + (cn & 3) * B_STAGE_BYTES + lrow * BQ_STRIDE + seg * 16, src);
                }
                CP_COMMIT();            // empty group keeps the count aligned at tail
            }

            // ---- consume stage c&3: 2 k32 steps, frag double-buffered ----
            unsigned bB = sbB + (c & 3) * B_STAGE_BYTES;
            unsigned a[2][2][4], bf[2][4][2];

            load_frags8(sbA, bB, aRow, aColB, bRow, bColB, 0, a[0], bf[0]);
            #pragma unroll
            for (int ks = 0; ks < 2; ks++) {
                int cur = ks & 1;
                if (ks < 1)
                    load_frags8(sbA, bB, aRow, aColB, bRow, bColB, 32,
                                a[cur ^ 1], bf[cur ^ 1]);
                #pragma unroll
                for (int i = 0; i < 2; i++)
                    #pragma unroll
                    for (int j = 0; j < 4; j++)
                        asm volatile(
                            "mma.sync.aligned.m16n8k32.row.col.s32.s8.s8.s32 "
                            "{%0,%1,%2,%3},{%4,%5,%6,%7},{%8,%9},{%0,%1,%2,%3};"
                            : "+r"(acc[i][j][0]), "+r"(acc[i][j][1]),
                              "+r"(acc[i][j][2]), "+r"(acc[i][j][3])
                            : "r"(a[cur][i][0]), "r"(a[cur][i][1]),
                              "r"(a[cur][i][2]), "r"(a[cur][i][3]),
                              "r"(bf[cur][j][0]), "r"(bf[cur][j][1]));
            }
        }

        // ---- per-warp epilogue over this warp's 32 cols ----
        int n0 = nt * TILE_N;
        float swv[8];
        #pragma unroll
        for (int j = 0; j < 4; j++)
            #pragma unroll
            for (int e2 = 0; e2 < 2; e2++)
                swv[j * 2 + e2] = g_sw[n0 + wn * 32 + j * 8 + t4 * 2 + e2];

        #pragma unroll
        for (int i = 0; i < 2; i++) {
            #pragma unroll
            for (int h = 0; h < 2; h++) {
                float fx = fxv[i * 2 + h];
                float m = -INFINITY;
                float z[8];
                #pragma unroll
                for (int j = 0; j < 4; j++) {
                    #pragma unroll
                    for (int e2 = 0; e2 < 2; e2++) {
                        int gc = n0 + wn * 32 + j * 8 + t4 * 2 + e2;
                        float v = fx * swv[j * 2 + e2] * (float)acc[i][j][h * 2 + e2];
                        z[j * 2 + e2] = (gc < CDIM) ? v : -INFINITY;
                        m = fmaxf(m, z[j * 2 + e2]);
                    }
                }
                m = fmaxf(m, __shfl_xor_sync(0xffffffffu, m, 1));
                m = fmaxf(m, __shfl_xor_sync(0xffffffffu, m, 2));
                float s = 0.0f;
                if (m > -1e37f) {
                    #pragma unroll
                    for (int j8 = 0; j8 < 8; j8++) s += __expf(z[j8] - m);
                }
                s += __shfl_xor_sync(0xffffffffu, s, 1);
                s += __shfl_xor_sync(0xffffffffu, s, 2);
                if (t4 == 0) {
                    int r = m0 + wm * 32 + i * 16 + h * 8 + g4;
                    size_t idx = (size_t)r * NPART + nt * 4 + wn;
                    g_pm[idx] = fmaxf(m, -3.0e38f);   // finite sentinel: NaN-safe merge
                    g_ps[idx] = s;
                }
            }
        }
    }
}

// ---------------- logsumexp merge + margin + NLL ----------------
__global__ void __launch_bounds__(256) reduce_kernel() {
    int b = blockIdx.x, tid = threadIdx.x;
    float M = -INFINITY, S = 0.0f;
    for (int i = tid; i < NPART; i += 256) {
        float m = g_pm[(size_t)b * NPART + i];
        float s = g_ps[(size_t)b * NPART + i];
        if (m > M) { S = S * __expf(M - m) + s; M = m; }
        else       { S += s * __expf(m - M); }
    }
    __shared__ float sm[256], ss[256];
    sm[tid] = M; ss[tid] = S;
    __syncthreads();
    for (int o = 128; o; o >>= 1) {
        if (tid < o) {
            float m2 = sm[tid + o], s2 = ss[tid + o];
            float m1 = sm[tid],     s1 = ss[tid];
            float mn = fmaxf(m1, m2);
            sm[tid] = mn;
            ss[tid] = s1 * __expf(m1 - mn) + s2 * __expf(m2 - mn);
        }
        __syncthreads();
    }
    if (tid == 0) {
        float Mf = sm[0], Sf = ss[0];
        float zg = SCALE_F * g_cosgt[b];
        float zm = zg - SCALE_F * MARGIN_F;
        // swap the gt term: remove (approx) unmargined, add exact margined
        Sf = Sf - expf(zg - Mf) + expf(zm - Mf);
        float lse = Mf + logf(Sf);
        g_nll[b] = lse - zm;
    }
}

__global__ void __launch_bounds__(512) mean_kernel(float* __restrict__ out) {
    __shared__ float sm[512];
    int t = threadIdx.x;
    sm[t] = g_nll[t];
    __syncthreads();
    for (int o = 256; o; o >>= 1) {
        if (t < o) sm[t] += sm[t + o];
        __syncthreads();
    }
    if (t == 0) out[0] = sm[0] * (1.0f / (float)BDIM);
}

// ---------------- launch ----------------
extern "C" void kernel_launch(void* const* d_in, const int* in_sizes, int n_in,
                              void* d_out, int out_size) {
    const float* x  = (const float*)d_in[0];
    const void*  gt = d_in[1];
    const float* wt = (const float*)d_in[2];
    float* out = (float*)d_out;

    static int smem_set = 0;
    if (!smem_set) {
        cudaFuncSetAttribute(gemm_softmax_kernel,
                             cudaFuncAttributeMaxDynamicSharedMemorySize, SMEM_DYN);
        smem_set = 1;
    }

    detect_gt_kernel<<<1, 512>>>((const int*)gt);
    norm_x_kernel<<<BDIM, 128>>>(x);
    norm_w_kernel<<<C_PAD, 128>>>(wt);
    cosgt_kernel<<<BDIM, 128>>>(gt, wt);
    gemm_softmax_kernel<<<dim3(GRIDX, 4), 512, SMEM_DYN>>>();
    reduce_kernel<<<BDIM, 256>>>();
    mean_kernel<<<1, 512>>>(out);
}

// round 10
// speedup vs baseline: 1.0229x; 1.0229x over previous
#include <cuda_runtime.h>
#include <cuda_bf16.h>
#include <math.h>

#define BDIM 512
#define DDIM 512
#define CDIM 100000
#define SCALE_F 64.0f
#define MARGIN_F 0.35f

#define TILE_N 128
#define NT 782
#define C_PAD (NT * TILE_N)
#define NCHUNK NT
#define GRIDX 37                       // 37*4 = 148 CTAs = 1 wave

#define ASTRIDE_B 1040
#define BSTRIDE_B 144
#define A_SMEM_BYTES (128 * ASTRIDE_B)             // 133120
#define B_STAGE_BYTES (128 * BSTRIDE_B)            // 18432
#define OFF_B A_SMEM_BYTES
#define OFF_RED (A_SMEM_BYTES + 2 * B_STAGE_BYTES) // 169984
#define SMEM_DYN (OFF_RED + 128 * 4 * 4)           // 172032

__device__ __nv_bfloat16 g_xb[BDIM * DDIM];
__device__ float         g_xn[BDIM * DDIM];
__device__ __nv_bfloat16 g_wb[(size_t)C_PAD * DDIM];
__device__ float         g_pm[BDIM * NCHUNK];
__device__ float         g_ps[BDIM * NCHUNK];
__device__ float         g_cosgt[BDIM];
__device__ float         g_nll[BDIM];
__device__ int           g_is64;
__device__ int           g_flags[NT];
__device__ int           g_cnt[NT];

__device__ __forceinline__ unsigned smem_u32(const void* p) {
    unsigned a;
    asm("{ .reg .u64 t; cvta.to.shared.u64 t, %1; cvt.u32.u64 %0, t; }" : "=r"(a) : "l"(p));
    return a;
}
#define CP_ASYNC16(d, s) asm volatile("cp.async.cg.shared.global [%0], [%1], 16;" :: "r"(d), "l"(s) : "memory")
#define CP_COMMIT()  asm volatile("cp.async.commit_group;" ::: "memory")
#define CP_WAIT1()   asm volatile("cp.async.wait_group 1;" ::: "memory")
#define CP_WAIT0()   asm volatile("cp.async.wait_group 0;" ::: "memory")

__device__ __forceinline__ uint2 pack_bf16x4(float4 v, float rn) {
    __nv_bfloat162 a = __floats2bfloat162_rn(v.x * rn, v.y * rn);
    __nv_bfloat162 b = __floats2bfloat162_rn(v.z * rn, v.w * rn);
    uint2 u; u.x = *(unsigned*)&a; u.y = *(unsigned*)&b; return u;
}

// ---------------- small kernels ----------------
__global__ void detect_gt_kernel(const int* __restrict__ graw) {
    __shared__ int any_nz;
    if (threadIdx.x == 0) any_nz = 0;
    __syncthreads();
    if ((threadIdx.x & 1) && graw[threadIdx.x] != 0) any_nz = 1;
    __syncthreads();
    if (threadIdx.x == 0) g_is64 = any_nz ? 0 : 1;
}

__global__ void zero_flags_kernel() {
    int i = blockIdx.x * blockDim.x + threadIdx.x;
    if (i < NT) { g_flags[i] = 0; g_cnt[i] = 0; }
}

__global__ void __launch_bounds__(128) norm_x_kernel(const float* __restrict__ x) {
    int b = blockIdx.x, tid = threadIdx.x;
    float4 v = ((const float4*)(x + (size_t)b * DDIM))[tid];
    float ss = v.x*v.x + v.y*v.y + v.z*v.z + v.w*v.w;
    #pragma unroll
    for (int o = 16; o; o >>= 1) ss += __shfl_xor_sync(0xffffffffu, ss, o);
    __shared__ float sm[4];
    if ((tid & 31) == 0) sm[tid >> 5] = ss;
    __syncthreads();
    float tot = sm[0] + sm[1] + sm[2] + sm[3];
    float r = 1.0f / fmaxf(sqrtf(tot), 1e-12f);
    float4 n = make_float4(v.x*r, v.y*r, v.z*r, v.w*r);
    ((float4*)(g_xn + (size_t)b * DDIM))[tid] = n;
    __nv_bfloat162* dst = (__nv_bfloat162*)(g_xb + (size_t)b * DDIM);
    dst[tid * 2 + 0] = __floats2bfloat162_rn(n.x, n.y);
    dst[tid * 2 + 1] = __floats2bfloat162_rn(n.z, n.w);
}

// persistent W-normalizer, runs CONCURRENT with the GEMM (flag per 128-row tile)
__global__ void __launch_bounds__(128) norm_w_persist(const float* __restrict__ wt) {
    int w = threadIdx.x >> 5, l = threadIdx.x & 31;
    #pragma unroll 1
    for (int base = blockIdx.x * 4; base < C_PAD; base += 148 * 4) {
        int r = base + w;
        float4 v0, v1, v2, v3;
        float ssq = 0.0f;
        if (r < CDIM) {
            const float4* src = (const float4*)(wt + (size_t)r * DDIM);
            v0 = src[l]; v1 = src[l + 32]; v2 = src[l + 64]; v3 = src[l + 96];
            ssq = v0.x*v0.x + v0.y*v0.y + v0.z*v0.z + v0.w*v0.w
                + v1.x*v1.x + v1.y*v1.y + v1.z*v1.z + v1.w*v1.w
                + v2.x*v2.x + v2.y*v2.y + v2.z*v2.z + v2.w*v2.w
                + v3.x*v3.x + v3.y*v3.y + v3.z*v3.z + v3.w*v3.w;
        } else {
            v0 = v1 = v2 = v3 = make_float4(0.f, 0.f, 0.f, 0.f);
        }
        #pragma unroll
        for (int o = 16; o; o >>= 1) ssq += __shfl_xor_sync(0xffffffffu, ssq, o);
        float rn = 1.0f / fmaxf(sqrtf(ssq), 1e-12f);
        uint2* dst = (uint2*)(g_wb + (size_t)r * DDIM);
        dst[l]      = pack_bf16x4(v0, rn);
        dst[l + 32] = pack_bf16x4(v1, rn);
        dst[l + 64] = pack_bf16x4(v2, rn);
        dst[l + 96] = pack_bf16x4(v3, rn);
        __threadfence();
        __syncwarp();
        if (l == 0) {
            if (atomicAdd(&g_cnt[r >> 7], 1) == 127)
                atomicExch(&g_flags[r >> 7], 1);
        }
    }
}

__global__ void __launch_bounds__(128) cosgt_kernel(const void* __restrict__ gt,
                                                    const float* __restrict__ wt) {
    int b = blockIdx.x, tid = threadIdx.x;
    long long c = g_is64 ? ((const long long*)gt)[b] : (long long)((const int*)gt)[b];
    float4 w  = ((const float4*)(wt + (size_t)c * DDIM))[tid];
    float4 xn = ((const float4*)(g_xn + (size_t)b * DDIM))[tid];
    float ss = w.x*w.x + w.y*w.y + w.z*w.z + w.w*w.w;
    float dp = w.x*xn.x + w.y*xn.y + w.z*xn.z + w.w*xn.w;
    #pragma unroll
    for (int o = 16; o; o >>= 1) {
        ss += __shfl_xor_sync(0xffffffffu, ss, o);
        dp += __shfl_xor_sync(0xffffffffu, dp, o);
    }
    __shared__ float sms[4], smd[4];
    if ((tid & 31) == 0) { sms[tid >> 5] = ss; smd[tid >> 5] = dp; }
    __syncthreads();
    if (tid == 0) {
        float tss = sms[0] + sms[1] + sms[2] + sms[3];
        float tdp = smd[0] + smd[1] + smd[2] + smd[3];
        g_cosgt[b] = tdp / fmaxf(sqrtf(tss), 1e-12f);
    }
}

// fallback: this CTA normalizes one tile itself (idempotent, duplicate-safe)
__device__ void self_norm_tile(const float* __restrict__ wt, int nt, int tid) {
    int r = nt * TILE_N + (tid >> 1);
    int half = tid & 1;
    bool valid = (r < CDIM);
    const float4* src = (const float4*)(wt + (size_t)(valid ? r : 0) * DDIM) + half * 64;
    float ssq = 0.0f;
    if (valid) {
        #pragma unroll 8
        for (int i = 0; i < 64; i++) {
            float4 v = src[i];
            ssq += v.x*v.x + v.y*v.y + v.z*v.z + v.w*v.w;
        }
    }
    ssq += __shfl_xor_sync(0xffffffffu, ssq, 1);
    float rn = 1.0f / fmaxf(sqrtf(ssq), 1e-12f);
    __nv_bfloat162* dst = (__nv_bfloat162*)(g_wb + (size_t)r * DDIM) + half * 128;
    if (valid) {
        for (int i = 0; i < 64; i++) {
            float4 v = src[i];
            dst[i * 2 + 0] = __floats2bfloat162_rn(v.x * rn, v.y * rn);
            dst[i * 2 + 1] = __floats2bfloat162_rn(v.z * rn, v.w * rn);
        }
    } else {
        __nv_bfloat162 z = __floats2bfloat162_rn(0.f, 0.f);
        for (int i = 0; i < 128; i++) dst[i] = z;
    }
}

__device__ __forceinline__ void wait_tile(const float* __restrict__ wt, int nt,
                                          int tid, int* s_to) {
    if (tid == 0) {
        int to = 0;
        if (*(volatile int*)&g_flags[nt] == 0) {
            int it = 0;
            while (*(volatile int*)&g_flags[nt] == 0) {
                __nanosleep(128);
                if (++it > 40000) { to = 1; break; }
            }
        }
        *s_to = to;
    }
    __syncthreads();
    if (*s_to) {
        self_norm_tile(wt, nt, tid);
        __syncthreads();
    }
    __threadfence();   // acquire ordering for g_wb reads
}

// ---------------- R3 GEMM + fused softmax partials (+ tile waits) ----------------
__global__ void __launch_bounds__(256, 1) gemm_softmax_kernel(const float* __restrict__ wt) {
    extern __shared__ char smem[];
    unsigned sbase = smem_u32(smem);
    unsigned sbA = sbase;
    unsigned sbB = sbase + OFF_B;
    float (*red)[4] = (float(*)[4])(smem + OFF_RED);
    __shared__ int s_to;

    int tid  = threadIdx.x;
    int lane = tid & 31;
    int warp = tid >> 5;
    int wm = warp >> 2;
    int wn = warp & 3;
    int m0 = blockIdx.y * 128;
    int bx = blockIdx.x;

    wait_tile(wt, bx, tid, &s_to);

    int seg = tid & 7;
    int rb  = tid >> 3;
    {
        const char* src = (const char*)g_wb + (size_t)(bx * TILE_N) * 1024 + seg * 16;
        #pragma unroll
        for (int q = 0; q < 4; q++) {
            int row = rb + q * 32;
            CP_ASYNC16(sbB + row * BSTRIDE_B + seg * 16, src + (size_t)row * 1024);
        }
        CP_COMMIT();
    }
    #pragma unroll
    for (int it = 0; it < 32; it++) {
        int idx = it * 256 + tid;
        int r = idx >> 6, s = idx & 63;
        uint4 v = *(const uint4*)(g_xb + (size_t)(m0 + r) * DDIM + s * 8);
        *(uint4*)(smem + r * ASTRIDE_B + s * 16) = v;
    }

    int g4 = lane >> 2, t4 = lane & 3;

    #pragma unroll 1
    for (int nt = bx; nt < NT; nt += GRIDX) {
        float acc[4][4][4];
        #pragma unroll
        for (int i = 0; i < 4; i++)
            #pragma unroll
            for (int j = 0; j < 4; j++)
                #pragma unroll
                for (int e = 0; e < 4; e++) acc[i][j][e] = 0.0f;

        const char* bsrc = (const char*)g_wb + (size_t)(nt * TILE_N) * 1024 + seg * 16;

        #pragma unroll 1
        for (int ck = 0; ck < 8; ck++) {
            if (ck < 7) {
                int nb = (ck + 1) & 1;
                #pragma unroll
                for (int q = 0; q < 4; q++) {
                    int row = rb + q * 32;
                    CP_ASYNC16(sbB + nb * B_STAGE_BYTES + row * BSTRIDE_B + seg * 16,
                               bsrc + (size_t)row * 1024 + (ck + 1) * 128);
                }
                CP_COMMIT();
                CP_WAIT1();
            } else {
                CP_WAIT0();
            }
            __syncthreads();

            unsigned bB = sbB + (ck & 1) * B_STAGE_BYTES;
            #pragma unroll
            for (int k16 = 0; k16 < 4; k16++) {
                unsigned a[4][4];
                #pragma unroll
                for (int i = 0; i < 4; i++) {
                    int r   = wm * 64 + i * 16 + (lane & 15);
                    int col = k16 * 16 + ((lane >> 4) << 3);
                    unsigned addr = sbA + r * ASTRIDE_B + col * 2;
                    asm volatile("ldmatrix.sync.aligned.m8n8.x4.shared.b16 {%0,%1,%2,%3}, [%4];"
                                 : "=r"(a[i][0]), "=r"(a[i][1]), "=r"(a[i][2]), "=r"(a[i][3])
                                 : "r"(addr));
                }
                unsigned bfr[4][2];
                #pragma unroll
                for (int j2 = 0; j2 < 2; j2++) {
                    int nrow = wn * 32 + j2 * 16 + (lane & 7) + ((lane >> 4) << 3);
                    int col  = k16 * 16 + (((lane >> 3) & 1) << 3);
                    unsigned addr = bB + nrow * BSTRIDE_B + col * 2;
                    unsigned r0, r1, r2, r3;
                    asm volatile("ldmatrix.sync.aligned.m8n8.x4.shared.b16 {%0,%1,%2,%3}, [%4];"
                                 : "=r"(r0), "=r"(r1), "=r"(r2), "=r"(r3) : "r"(addr));
                    bfr[j2 * 2 + 0][0] = r0; bfr[j2 * 2 + 0][1] = r1;
                    bfr[j2 * 2 + 1][0] = r2; bfr[j2 * 2 + 1][1] = r3;
                }
                #pragma unroll
                for (int i = 0; i < 4; i++)
                    #pragma unroll
                    for (int j = 0; j < 4; j++)
                        asm volatile(
                            "mma.sync.aligned.m16n8k16.row.col.f32.bf16.bf16.f32 "
                            "{%0,%1,%2,%3},{%4,%5,%6,%7},{%8,%9},{%0,%1,%2,%3};"
                            : "+f"(acc[i][j][0]), "+f"(acc[i][j][1]),
                              "+f"(acc[i][j][2]), "+f"(acc[i][j][3])
                            : "r"(a[i][0]), "r"(a[i][1]), "r"(a[i][2]), "r"(a[i][3]),
                              "r"(bfr[j][0]), "r"(bfr[j][1]));
            }
            __syncthreads();
        }

        if (nt + GRIDX < NT) {
            wait_tile(wt, nt + GRIDX, tid, &s_to);
            const char* src2 = (const char*)g_wb + (size_t)((nt + GRIDX) * TILE_N) * 1024 + seg * 16;
            #pragma unroll
            for (int q = 0; q < 4; q++) {
                int row = rb + q * 32;
                CP_ASYNC16(sbB + row * BSTRIDE_B + seg * 16, src2 + (size_t)row * 1024);
            }
            CP_COMMIT();
        }

        int n0 = nt * TILE_N;
        float rmax[8];
        #pragma unroll
        for (int i = 0; i < 4; i++) {
            #pragma unroll
            for (int h = 0; h < 2; h++) {
                float m = -INFINITY;
                #pragma unroll
                for (int j = 0; j < 4; j++) {
                    #pragma unroll
                    for (int e2 = 0; e2 < 2; e2++) {
                        int gc = n0 + wn * 32 + j * 8 + t4 * 2 + e2;
                        float z = (gc < CDIM) ? SCALE_F * acc[i][j][h * 2 + e2] : -INFINITY;
                        m = fmaxf(m, z);
                    }
                }
                m = fmaxf(m, __shfl_xor_sync(0xffffffffu, m, 1));
                m = fmaxf(m, __shfl_xor_sync(0xffffffffu, m, 2));
                rmax[i * 2 + h] = m;
            }
        }
        if (t4 == 0) {
            #pragma unroll
            for (int i = 0; i < 4; i++)
                #pragma unroll
                for (int h = 0; h < 2; h++)
                    red[wm * 64 + i * 16 + h * 8 + g4][wn] = rmax[i * 2 + h];
        }
        __syncthreads();
        float fmx[8];
        #pragma unroll
        for (int i = 0; i < 4; i++)
            #pragma unroll
            for (int h = 0; h < 2; h++) {
                int r = wm * 64 + i * 16 + h * 8 + g4;
                fmx[i * 2 + h] = fmaxf(fmaxf(red[r][0], red[r][1]),
                                       fmaxf(red[r][2], red[r][3]));
            }
        __syncthreads();

        float rsum[8];
        #pragma unroll
        for (int i = 0; i < 4; i++) {
            #pragma unroll
            for (int h = 0; h < 2; h++) {
                float s = 0.0f;
                #pragma unroll
                for (int j = 0; j < 4; j++) {
                    #pragma unroll
                    for (int e2 = 0; e2 < 2; e2++) {
                        int gc = n0 + wn * 32 + j * 8 + t4 * 2 + e2;
                        if (gc < CDIM)
                            s += __expf(SCALE_F * acc[i][j][h * 2 + e2] - fmx[i * 2 + h]);
                    }
                }
                s += __shfl_xor_sync(0xffffffffu, s, 1);
                s += __shfl_xor_sync(0xffffffffu, s, 2);
                rsum[i * 2 + h] = s;
            }
        }
        if (t4 == 0) {
            #pragma unroll
            for (int i = 0; i < 4; i++)
                #pragma unroll
                for (int h = 0; h < 2; h++)
                    red[wm * 64 + i * 16 + h * 8 + g4][wn] = rsum[i * 2 + h];
        }
        __syncthreads();
        if (wn == 0 && t4 == 0) {
            #pragma unroll
            for (int i = 0; i < 4; i++)
                #pragma unroll
                for (int h = 0; h < 2; h++) {
                    int r = wm * 64 + i * 16 + h * 8 + g4;
                    float S = red[r][0] + red[r][1] + red[r][2] + red[r][3];
                    g_pm[(m0 + r) * NCHUNK + nt] = fmx[i * 2 + h];
                    g_ps[(m0 + r) * NCHUNK + nt] = S;
                }
        }
        __syncthreads();
    }
}

__global__ void __launch_bounds__(256) reduce_kernel() {
    int b = blockIdx.x, tid = threadIdx.x;
    float M = -INFINITY, S = 0.0f;
    for (int i = tid; i < NCHUNK; i += 256) {
        float m = g_pm[b * NCHUNK + i];
        float s = g_ps[b * NCHUNK + i];
        if (m > M) { S = S * __expf(M - m) + s; M = m; }
        else       { S += s * __expf(m - M); }
    }
    __shared__ float sm[256], ss[256];
    sm[tid] = M; ss[tid] = S;
    __syncthreads();
    for (int o = 128; o; o >>= 1) {
        if (tid < o) {
            float m2 = sm[tid + o], s2 = ss[tid + o];
            float m1 = sm[tid],     s1 = ss[tid];
            float mn = fmaxf(m1, m2);
            sm[tid] = mn;
            ss[tid] = s1 * __expf(m1 - mn) + s2 * __expf(m2 - mn);
        }
        __syncthreads();
    }
    if (tid == 0) {
        float Mf = sm[0], Sf = ss[0];
        float zg = SCALE_F * g_cosgt[b];
        float zm = zg - SCALE_F * MARGIN_F;
        Sf = Sf - expf(zg - Mf) + expf(zm - Mf);
        float lse = Mf + logf(Sf);
        g_nll[b] = lse - zm;
    }
}

__global__ void __launch_bounds__(512) mean_kernel(float* __restrict__ out) {
    __shared__ float sm[512];
    int t = threadIdx.x;
    sm[t] = g_nll[t];
    __syncthreads();
    for (int o = 256; o; o >>= 1) {
        if (t < o) sm[t] += sm[t + o];
        __syncthreads();
    }
    if (t == 0) out[0] = sm[0] * (1.0f / (float)BDIM);
}

// ---------------- launch (fork-join for concurrent norm_w) ----------------
extern "C" void kernel_launch(void* const* d_in, const int* in_sizes, int n_in,
                              void* d_out, int out_size) {
    const float* x  = (const float*)d_in[0];
    const void*  gt = d_in[1];
    const float* wt = (const float*)d_in[2];
    float* out = (float*)d_out;

    static cudaStream_t s2 = nullptr;
    static cudaEvent_t ev_fork = nullptr, ev_join = nullptr;
    if (!s2) {
        cudaFuncSetAttribute(gemm_softmax_kernel,
                             cudaFuncAttributeMaxDynamicSharedMemorySize, SMEM_DYN);
        cudaStreamCreateWithFlags(&s2, cudaStreamNonBlocking);
        cudaEventCreateWithFlags(&ev_fork, cudaEventDisableTiming);
        cudaEventCreateWithFlags(&ev_join, cudaEventDisableTiming);
    }

    detect_gt_kernel<<<1, 512>>>((const int*)gt);
    norm_x_kernel<<<BDIM, 128>>>(x);
    cosgt_kernel<<<BDIM, 128>>>(gt, wt);
    zero_flags_kernel<<<(NT + 255) / 256, 256>>>();

    cudaEventRecord(ev_fork, 0);
    cudaStreamWaitEvent(s2, ev_fork, 0);
    norm_w_persist<<<148, 128, 0, s2>>>(wt);
    cudaEventRecord(ev_join, s2);

    gemm_softmax_kernel<<<dim3(GRIDX, 4), 256, SMEM_DYN>>>(wt);

    cudaStreamWaitEvent(0, ev_join, 0);
    reduce_kernel<<<BDIM, 256>>>();
    mean_kernel<<<1, 512>>>(out);
}

// round 11
// speedup vs baseline: 2.0594x; 2.0133x over previous
#include <cuda_runtime.h>
#include <cuda_bf16.h>
#include <math.h>

#define BDIM 512
#define DDIM 512
#define CDIM 100000
#define SCALE_F 64.0f
#define MARGIN_F 0.35f

#define TILE_N 128
#define NT 782                          // ceil(100000/128)
#define NCHUNK NT
#define GRIDX 37                        // 37*4 = 148 CTAs = 1 wave

#define ASTRIDE_B 1040                  // A smem row stride (512*2 + 16)
#define BSTRIDE_B 144                   // B smem row stride (64*2 + 16)
#define A_SMEM_BYTES (128 * ASTRIDE_B)              // 133120
#define B_STAGE_BYTES (128 * BSTRIDE_B)             // 18432
#define OFF_B A_SMEM_BYTES
#define OFF_RED (A_SMEM_BYTES + 2 * B_STAGE_BYTES)  // 169984
#define OFF_RSS (OFF_RED + 128 * 4 * 4)             // 172032
#define SMEM_DYN (OFF_RSS + 128 * 4)                // 172544

// ---------------- device scratch ----------------
__device__ __nv_bfloat16 g_xb[BDIM * DDIM];
__device__ float         g_xn[BDIM * DDIM];
__device__ float         g_pm[BDIM * NCHUNK];
__device__ float         g_ps[BDIM * NCHUNK];
__device__ float         g_cosgt[BDIM];
__device__ float         g_nll[BDIM];
__device__ int           g_is64;

// ---------------- helpers ----------------
__device__ __forceinline__ unsigned smem_u32(const void* p) {
    unsigned a;
    asm("{ .reg .u64 t; cvta.to.shared.u64 t, %1; cvt.u32.u64 %0, t; }" : "=r"(a) : "l"(p));
    return a;
}

__device__ __forceinline__ uint2 cvt_bf16x4(float4 v) {
    __nv_bfloat162 a = __floats2bfloat162_rn(v.x, v.y);
    __nv_bfloat162 b = __floats2bfloat162_rn(v.z, v.w);
    uint2 u; u.x = *(unsigned*)&a; u.y = *(unsigned*)&b; return u;
}

// ---------------- small kernels ----------------
__global__ void detect_gt_kernel(const int* __restrict__ graw) {
    __shared__ int any_nz;
    if (threadIdx.x == 0) any_nz = 0;
    __syncthreads();
    if ((threadIdx.x & 1) && graw[threadIdx.x] != 0) any_nz = 1;
    __syncthreads();
    if (threadIdx.x == 0) g_is64 = any_nz ? 0 : 1;
}

__global__ void __launch_bounds__(128) norm_x_kernel(const float* __restrict__ x) {
    int b = blockIdx.x, tid = threadIdx.x;
    float4 v = ((const float4*)(x + (size_t)b * DDIM))[tid];
    float ss = v.x*v.x + v.y*v.y + v.z*v.z + v.w*v.w;
    #pragma unroll
    for (int o = 16; o; o >>= 1) ss += __shfl_xor_sync(0xffffffffu, ss, o);
    __shared__ float sm[4];
    if ((tid & 31) == 0) sm[tid >> 5] = ss;
    __syncthreads();
    float tot = sm[0] + sm[1] + sm[2] + sm[3];
    float r = 1.0f / fmaxf(sqrtf(tot), 1e-12f);
    float4 n = make_float4(v.x*r, v.y*r, v.z*r, v.w*r);
    ((float4*)(g_xn + (size_t)b * DDIM))[tid] = n;
    __nv_bfloat162* dst = (__nv_bfloat162*)(g_xb + (size_t)b * DDIM);
    dst[tid * 2 + 0] = __floats2bfloat162_rn(n.x, n.y);
    dst[tid * 2 + 1] = __floats2bfloat162_rn(n.z, n.w);
}

__global__ void __launch_bounds__(128) cosgt_kernel(const void* __restrict__ gt,
                                                    const float* __restrict__ wt) {
    int b = blockIdx.x, tid = threadIdx.x;
    long long c = g_is64 ? ((const long long*)gt)[b] : (long long)((const int*)gt)[b];
    float4 w  = ((const float4*)(wt + (size_t)c * DDIM))[tid];
    float4 xn = ((const float4*)(g_xn + (size_t)b * DDIM))[tid];
    float ss = w.x*w.x + w.y*w.y + w.z*w.z + w.w*w.w;
    float dp = w.x*xn.x + w.y*xn.y + w.z*xn.z + w.w*xn.w;
    #pragma unroll
    for (int o = 16; o; o >>= 1) {
        ss += __shfl_xor_sync(0xffffffffu, ss, o);
        dp += __shfl_xor_sync(0xffffffffu, dp, o);
    }
    __shared__ float sms[4], smd[4];
    if ((tid & 31) == 0) { sms[tid >> 5] = ss; smd[tid >> 5] = dp; }
    __syncthreads();
    if (tid == 0) {
        float tss = sms[0] + sms[1] + sms[2] + sms[3];
        float tdp = smd[0] + smd[1] + smd[2] + smd[3];
        g_cosgt[b] = tdp / fmaxf(sqrtf(tss), 1e-12f);
    }
}

// ---------------- GEMM on RAW fp32 W (inline bf16 convert + norm in epilogue) ----------------
// grid (37, 4), 256 threads, 8 warps (2m x 4n), warp tile 64x32.
// Loader: LDG fp32 -> regs (double-buffered across chunks) -> CVT bf16 -> STS,
// accumulating per-row sum-of-squares on the fly. Epilogue multiplies by rsqrt.
__global__ void __launch_bounds__(256, 1) gemm_softmax_kernel(const float* __restrict__ wt) {
    extern __shared__ char smem[];
    unsigned sbase = smem_u32(smem);
    unsigned sbA = sbase;
    unsigned sbB = sbase + OFF_B;
    float (*red)[4] = (float(*)[4])(smem + OFF_RED);
    float* sRss = (float*)(smem + OFF_RSS);

    int tid  = threadIdx.x;
    int lane = tid & 31;
    int warp = tid >> 5;
    int wm = warp >> 2;       // 0..1
    int wn = warp & 3;        // 0..3
    int m0 = blockIdx.y * 128;
    int bx = blockIdx.x;

    // loader mapping: seg = 16B fp32 segment (16 per 256B chunk-row), rb = base row
    int seg = tid & 15;       // 0..15
    int rb  = tid >> 4;       // 0..15
    const float4* wsrc = (const float4*)wt;   // float4 index: row*128 + ck*16 + seg

    // ---- stage A[128x512] bf16 into SMEM (once) ----
    #pragma unroll
    for (int it = 0; it < 32; it++) {
        int idx = it * 256 + tid;
        int r = idx >> 6, s = idx & 63;
        uint4 v = *(const uint4*)(g_xb + (size_t)(m0 + r) * DDIM + s * 8);
        *(uint4*)(smem + r * ASTRIDE_B + s * 16) = v;
    }

    int g4 = lane >> 2, t4 = lane & 3;

    // ---- prologue: load chunk 0 of first tile into regs ----
    float4 vreg[8];
    #pragma unroll
    for (int q = 0; q < 8; q++) {
        int rg = bx * TILE_N + rb + q * 16;
        vreg[q] = (rg < CDIM) ? wsrc[(size_t)rg * 128 + seg]
                              : make_float4(0.f, 0.f, 0.f, 0.f);
    }

    #pragma unroll 1
    for (int nt = bx; nt < NT; nt += GRIDX) {
        float acc[4][4][4];
        #pragma unroll
        for (int i = 0; i < 4; i++)
            #pragma unroll
            for (int j = 0; j < 4; j++)
                #pragma unroll
                for (int e = 0; e < 4; e++) acc[i][j][e] = 0.0f;

        float ssq[8];
        #pragma unroll
        for (int q = 0; q < 8; q++) ssq[q] = 0.0f;

        #pragma unroll 1
        for (int ck = 0; ck < 8; ck++) {
            __syncthreads();   // stage (ck&1) fully consumed by all warps

            // convert regs(ck) -> bf16 stage, accumulate ssq
            unsigned bst = sbB + (ck & 1) * B_STAGE_BYTES;
            #pragma unroll
            for (int q = 0; q < 8; q++) {
                float4 v = vreg[q];
                ssq[q] += v.x*v.x + v.y*v.y + v.z*v.z + v.w*v.w;
                int row = rb + q * 16;
                *(uint2*)(smem + OFF_B + (ck & 1) * B_STAGE_BYTES
                          + row * BSTRIDE_B + seg * 8) = cvt_bf16x4(v);
            }
            (void)bst;

            if (ck == 7) {
                // reduce ssq across the 16 seg-lanes (same rb) and publish
                #pragma unroll
                for (int q = 0; q < 8; q++) {
                    float s = ssq[q];
                    s += __shfl_xor_sync(0xffffffffu, s, 1);
                    s += __shfl_xor_sync(0xffffffffu, s, 2);
                    s += __shfl_xor_sync(0xffffffffu, s, 4);
                    s += __shfl_xor_sync(0xffffffffu, s, 8);
                    if (seg == 0) sRss[rb + q * 16] = s;
                }
            } else {
                // load chunk ck+1 into regs (latency hidden by MMA below)
                #pragma unroll
                for (int q = 0; q < 8; q++) {
                    int rg = nt * TILE_N + rb + q * 16;
                    vreg[q] = (rg < CDIM) ? wsrc[(size_t)rg * 128 + (ck + 1) * 16 + seg]
                                          : make_float4(0.f, 0.f, 0.f, 0.f);
                }
            }
            __syncthreads();   // stage (ck&1) ready (and sRss visible after ck=7)

            // ---- MMA over stage ck&1: 4 k16 steps ----
            unsigned bB = sbB + (ck & 1) * B_STAGE_BYTES;
            #pragma unroll
            for (int k16 = 0; k16 < 4; k16++) {
                unsigned a[4][4];
                #pragma unroll
                for (int i = 0; i < 4; i++) {
                    int r   = wm * 64 + i * 16 + (lane & 15);
                    int col = k16 * 16 + ((lane >> 4) << 3);
                    unsigned addr = sbA + r * ASTRIDE_B + col * 2;
                    asm volatile("ldmatrix.sync.aligned.m8n8.x4.shared.b16 {%0,%1,%2,%3}, [%4];"
                                 : "=r"(a[i][0]), "=r"(a[i][1]), "=r"(a[i][2]), "=r"(a[i][3])
                                 : "r"(addr));
                }
                unsigned bfr[4][2];
                #pragma unroll
                for (int j2 = 0; j2 < 2; j2++) {
                    int nrow = wn * 32 + j2 * 16 + (lane & 7) + ((lane >> 4) << 3);
                    int col  = k16 * 16 + (((lane >> 3) & 1) << 3);
                    unsigned addr = bB + nrow * BSTRIDE_B + col * 2;
                    unsigned r0, r1, r2, r3;
                    asm volatile("ldmatrix.sync.aligned.m8n8.x4.shared.b16 {%0,%1,%2,%3}, [%4];"
                                 : "=r"(r0), "=r"(r1), "=r"(r2), "=r"(r3) : "r"(addr));
                    bfr[j2 * 2 + 0][0] = r0; bfr[j2 * 2 + 0][1] = r1;
                    bfr[j2 * 2 + 1][0] = r2; bfr[j2 * 2 + 1][1] = r3;
                }
                #pragma unroll
                for (int i = 0; i < 4; i++)
                    #pragma unroll
                    for (int j = 0; j < 4; j++)
                        asm volatile(
                            "mma.sync.aligned.m16n8k16.row.col.f32.bf16.bf16.f32 "
                            "{%0,%1,%2,%3},{%4,%5,%6,%7},{%8,%9},{%0,%1,%2,%3};"
                            : "+f"(acc[i][j][0]), "+f"(acc[i][j][1]),
                              "+f"(acc[i][j][2]), "+f"(acc[i][j][3])
                            : "r"(a[i][0]), "r"(a[i][1]), "r"(a[i][2]), "r"(a[i][3]),
                              "r"(bfr[j][0]), "r"(bfr[j][1]));
            }
        }

        // prefetch chunk 0 of next tile (loads overlap the epilogue)
        if (nt + GRIDX < NT) {
            #pragma unroll
            for (int q = 0; q < 8; q++) {
                int rg = (nt + GRIDX) * TILE_N + rb + q * 16;
                vreg[q] = (rg < CDIM) ? wsrc[(size_t)rg * 128 + seg]
                                      : make_float4(0.f, 0.f, 0.f, 0.f);
            }
        }

        // ---- epilogue: z = SCALE * acc * rsqrt(||w||^2); per-row (max, sumexp) ----
        int n0 = nt * TILE_N;
        float rn[8];
        #pragma unroll
        for (int j = 0; j < 4; j++)
            #pragma unroll
            for (int e2 = 0; e2 < 2; e2++) {
                int tc = wn * 32 + j * 8 + t4 * 2 + e2;
                rn[j * 2 + e2] = rsqrtf(fmaxf(sRss[tc], 1e-30f)) * SCALE_F;
            }

        float rmax[8];
        #pragma unroll
        for (int i = 0; i < 4; i++) {
            #pragma unroll
            for (int h = 0; h < 2; h++) {
                float m = -INFINITY;
                #pragma unroll
                for (int j = 0; j < 4; j++) {
                    #pragma unroll
                    for (int e2 = 0; e2 < 2; e2++) {
                        int gc = n0 + wn * 32 + j * 8 + t4 * 2 + e2;
                        float z = (gc < CDIM) ? rn[j * 2 + e2] * acc[i][j][h * 2 + e2]
                                              : -INFINITY;
                        m = fmaxf(m, z);
                    }
                }
                m = fmaxf(m, __shfl_xor_sync(0xffffffffu, m, 1));
                m = fmaxf(m, __shfl_xor_sync(0xffffffffu, m, 2));
                rmax[i * 2 + h] = m;
            }
        }
        if (t4 == 0) {
            #pragma unroll
            for (int i = 0; i < 4; i++)
                #pragma unroll
                for (int h = 0; h < 2; h++)
                    red[wm * 64 + i * 16 + h * 8 + g4][wn] = rmax[i * 2 + h];
        }
        __syncthreads();
        float fmx[8];
        #pragma unroll
        for (int i = 0; i < 4; i++)
            #pragma unroll
            for (int h = 0; h < 2; h++) {
                int r = wm * 64 + i * 16 + h * 8 + g4;
                fmx[i * 2 + h] = fmaxf(fmaxf(red[r][0], red[r][1]),
                                       fmaxf(red[r][2], red[r][3]));
            }
        __syncthreads();

        float rsum[8];
        #pragma unroll
        for (int i = 0; i < 4; i++) {
            #pragma unroll
            for (int h = 0; h < 2; h++) {
                float s = 0.0f;
                #pragma unroll
                for (int j = 0; j < 4; j++) {
                    #pragma unroll
                    for (int e2 = 0; e2 < 2; e2++) {
                        int gc = n0 + wn * 32 + j * 8 + t4 * 2 + e2;
                        if (gc < CDIM)
                            s += __expf(rn[j * 2 + e2] * acc[i][j][h * 2 + e2]
                                        - fmx[i * 2 + h]);
                    }
                }
                s += __shfl_xor_sync(0xffffffffu, s, 1);
                s += __shfl_xor_sync(0xffffffffu, s, 2);
                rsum[i * 2 + h] = s;
            }
        }
        if (t4 == 0) {
            #pragma unroll
            for (int i = 0; i < 4; i++)
                #pragma unroll
                for (int h = 0; h < 2; h++)
                    red[wm * 64 + i * 16 + h * 8 + g4][wn] = rsum[i * 2 + h];
        }
        __syncthreads();
        if (wn == 0 && t4 == 0) {
            #pragma unroll
            for (int i = 0; i < 4; i++)
                #pragma unroll
                for (int h = 0; h < 2; h++) {
                    int r = wm * 64 + i * 16 + h * 8 + g4;
                    float S = red[r][0] + red[r][1] + red[r][2] + red[r][3];
                    g_pm[(m0 + r) * NCHUNK + nt] = fmx[i * 2 + h];
                    g_ps[(m0 + r) * NCHUNK + nt] = S;
                }
        }
        __syncthreads();
    }
}

// ---------------- logsumexp merge + margin + NLL ----------------
__global__ void __launch_bounds__(256) reduce_kernel() {
    int b = blockIdx.x, tid = threadIdx.x;
    float M = -INFINITY, S = 0.0f;
    for (int i = tid; i < NCHUNK; i += 256) {
        float m = g_pm[b * NCHUNK + i];
        float s = g_ps[b * NCHUNK + i];
        if (m > M) { S = S * __expf(M - m) + s; M = m; }
        else       { S += s * __expf(m - M); }
    }
    __shared__ float sm[256], ss[256];
    sm[tid] = M; ss[tid] = S;
    __syncthreads();
    for (int o = 128; o; o >>= 1) {
        if (tid < o) {
            float m2 = sm[tid + o], s2 = ss[tid + o];
            float m1 = sm[tid],     s1 = ss[tid];
            float mn = fmaxf(m1, m2);
            sm[tid] = mn;
            ss[tid] = s1 * __expf(m1 - mn) + s2 * __expf(m2 - mn);
        }
        __syncthreads();
    }
    if (tid == 0) {
        float Mf = sm[0], Sf = ss[0];
        float zg = SCALE_F * g_cosgt[b];
        float zm = zg - SCALE_F * MARGIN_F;
        Sf = Sf - expf(zg - Mf) + expf(zm - Mf);
        float lse = Mf + logf(Sf);
        g_nll[b] = lse - zm;
    }
}

__global__ void __launch_bounds__(512) mean_kernel(float* __restrict__ out) {
    __shared__ float sm[512];
    int t = threadIdx.x;
    sm[t] = g_nll[t];
    __syncthreads();
    for (int o = 256; o; o >>= 1) {
        if (t < o) sm[t] += sm[t + o];
        __syncthreads();
    }
    if (t == 0) out[0] = sm[0] * (1.0f / (float)BDIM);
}

// ---------------- launch ----------------
extern "C" void kernel_launch(void* const* d_in, const int* in_sizes, int n_in,
                              void* d_out, int out_size) {
    const float* x  = (const float*)d_in[0];
    const void*  gt = d_in[1];
    const float* wt = (const float*)d_in[2];
    float* out = (float*)d_out;

    static int smem_set = 0;
    if (!smem_set) {
        cudaFuncSetAttribute(gemm_softmax_kernel,
                             cudaFuncAttributeMaxDynamicSharedMemorySize, SMEM_DYN);
        smem_set = 1;
    }

    detect_gt_kernel<<<1, 512>>>((const int*)gt);
    norm_x_kernel<<<BDIM, 128>>>(x);
    cosgt_kernel<<<BDIM, 128>>>(gt, wt);
    gemm_softmax_kernel<<<dim3(GRIDX, 4), 256, SMEM_DYN>>>(wt);
    reduce_kernel<<<BDIM, 256>>>();
    mean_kernel<<<1, 512>>>(out);
}

// round 12
// speedup vs baseline: 2.1758x; 1.0565x over previous
#include <cuda_runtime.h>
#include <cuda_bf16.h>
#include <math.h>

#define BDIM 512
#define DDIM 512
#define CDIM 100000
#define SCALE_F 64.0f
#define MARGIN_F 0.35f

#define TILE_N 128
#define NT 782                          // ceil(100000/128)
#define NPART (NT * 4)                  // per-row partials: 2 groups x 2 wn per tile
#define GRIDX 37                        // 37*4 = 148 CTAs = 1 wave

#define ASTRIDE_B 1040                  // A smem row stride (512*2 + 16)
#define BSTRIDE_B 144                   // B smem row stride (64*2 + 16)
#define A_SMEM_BYTES (128 * ASTRIDE_B)              // 133120
#define G_STAGE (64 * BSTRIDE_B)                    // 9216 (64 rows per group)
#define OFF_B A_SMEM_BYTES
#define OFF_RSS (OFF_B + 2 * 2 * G_STAGE)           // 169984
#define SMEM_DYN (OFF_RSS + 2 * 64 * 4)             // 170496

// ---------------- device scratch ----------------
__device__ __nv_bfloat16 g_xb[BDIM * DDIM];
__device__ float         g_xn[BDIM * DDIM];
__device__ float         g_pm[(size_t)BDIM * NPART];
__device__ float         g_ps[(size_t)BDIM * NPART];
__device__ float         g_cosgt[BDIM];
__device__ float         g_nll[BDIM];
__device__ int           g_is64;

// ---------------- helpers ----------------
__device__ __forceinline__ unsigned smem_u32(const void* p) {
    unsigned a;
    asm("{ .reg .u64 t; cvta.to.shared.u64 t, %1; cvt.u32.u64 %0, t; }" : "=r"(a) : "l"(p));
    return a;
}
#define BAR_G(id) asm volatile("bar.sync %0, 128;" :: "r"(id) : "memory")

__device__ __forceinline__ uint2 cvt_bf16x4(float4 v) {
    __nv_bfloat162 a = __floats2bfloat162_rn(v.x, v.y);
    __nv_bfloat162 b = __floats2bfloat162_rn(v.z, v.w);
    uint2 u; u.x = *(unsigned*)&a; u.y = *(unsigned*)&b; return u;
}

// ---------------- small kernels ----------------
__global__ void detect_gt_kernel(const int* __restrict__ graw) {
    __shared__ int any_nz;
    if (threadIdx.x == 0) any_nz = 0;
    __syncthreads();
    if ((threadIdx.x & 1) && graw[threadIdx.x] != 0) any_nz = 1;
    __syncthreads();
    if (threadIdx.x == 0) g_is64 = any_nz ? 0 : 1;
}

__global__ void __launch_bounds__(128) norm_x_kernel(const float* __restrict__ x) {
    int b = blockIdx.x, tid = threadIdx.x;
    float4 v = ((const float4*)(x + (size_t)b * DDIM))[tid];
    float ss = v.x*v.x + v.y*v.y + v.z*v.z + v.w*v.w;
    #pragma unroll
    for (int o = 16; o; o >>= 1) ss += __shfl_xor_sync(0xffffffffu, ss, o);
    __shared__ float sm[4];
    if ((tid & 31) == 0) sm[tid >> 5] = ss;
    __syncthreads();
    float tot = sm[0] + sm[1] + sm[2] + sm[3];
    float r = 1.0f / fmaxf(sqrtf(tot), 1e-12f);
    float4 n = make_float4(v.x*r, v.y*r, v.z*r, v.w*r);
    ((float4*)(g_xn + (size_t)b * DDIM))[tid] = n;
    __nv_bfloat162* dst = (__nv_bfloat162*)(g_xb + (size_t)b * DDIM);
    dst[tid * 2 + 0] = __floats2bfloat162_rn(n.x, n.y);
    dst[tid * 2 + 1] = __floats2bfloat162_rn(n.z, n.w);
}

__global__ void __launch_bounds__(128) cosgt_kernel(const void* __restrict__ gt,
                                                    const float* __restrict__ wt) {
    int b = blockIdx.x, tid = threadIdx.x;
    long long c = g_is64 ? ((const long long*)gt)[b] : (long long)((const int*)gt)[b];
    float4 w  = ((const float4*)(wt + (size_t)c * DDIM))[tid];
    float4 xn = ((const float4*)(g_xn + (size_t)b * DDIM))[tid];
    float ss = w.x*w.x + w.y*w.y + w.z*w.z + w.w*w.w;
    float dp = w.x*xn.x + w.y*xn.y + w.z*xn.z + w.w*xn.w;
    #pragma unroll
    for (int o = 16; o; o >>= 1) {
        ss += __shfl_xor_sync(0xffffffffu, ss, o);
        dp += __shfl_xor_sync(0xffffffffu, dp, o);
    }
    __shared__ float sms[4], smd[4];
    if ((tid & 31) == 0) { sms[tid >> 5] = ss; smd[tid >> 5] = dp; }
    __syncthreads();
    if (tid == 0) {
        float tss = sms[0] + sms[1] + sms[2] + sms[3];
        float tdp = smd[0] + smd[1] + smd[2] + smd[3];
        g_cosgt[b] = tdp / fmaxf(sqrtf(tss), 1e-12f);
    }
}

// ---------------- GEMM, two independent warp-groups per CTA ----------------
// grid (37, 4), 256 threads. Group g = warps g*4..g*4+3 handles output cols
// [nt*128 + g*64, +64) with its OWN B stages + named barrier (id g+1).
// A [128x512] bf16 staged once, shared read-only.
__global__ void __launch_bounds__(256, 1) gemm_softmax_kernel(const float* __restrict__ wt) {
    extern __shared__ char smem[];
    unsigned sbA = smem_u32(smem);

    int tid  = threadIdx.x;
    int lane = tid & 31;
    int warp = tid >> 5;
    int g    = warp >> 2;       // group 0/1
    int gw   = warp & 3;        // warp in group
    int wm   = gw >> 1;         // 0..1 (m: 64-row warp tiles)
    int wn   = gw & 1;          // 0..1 (n: 32-col warp tiles within group's 64)
    int m0 = blockIdx.y * 128;
    int bx = blockIdx.x;
    int barid = g + 1;

    int gtid = tid & 127;
    int seg = gtid & 15;        // float4 segment within 64-fp32 chunk row
    int rb  = gtid >> 4;        // 0..7
    const float4* wsrc = (const float4*)wt;

    unsigned sbBg = sbA + OFF_B + g * (2 * G_STAGE);
    float* sRssG  = (float*)(smem + OFF_RSS) + g * 64;

    // ---- stage A[128x512] bf16 (all 256 threads) ----
    #pragma unroll
    for (int it = 0; it < 32; it++) {
        int idx = it * 256 + tid;
        int r = idx >> 6, s = idx & 63;
        uint4 v = *(const uint4*)(g_xb + (size_t)(m0 + r) * DDIM + s * 8);
        *(uint4*)(smem + r * ASTRIDE_B + s * 16) = v;
    }

    // ---- prologue: chunk 0 of first tile (group rows) ----
    float4 vreg[8];
    #pragma unroll
    for (int q = 0; q < 8; q++) {
        int rg = bx * TILE_N + g * 64 + rb + q * 8;
        vreg[q] = (rg < CDIM) ? wsrc[(size_t)rg * 128 + seg]
                              : make_float4(0.f, 0.f, 0.f, 0.f);
    }
    __syncthreads();   // A visible to all; groups independent hereafter

    int g4 = lane >> 2, t4 = lane & 3;

    #pragma unroll 1
    for (int nt = bx; nt < NT; nt += GRIDX) {
        float acc[4][4][4];
        #pragma unroll
        for (int i = 0; i < 4; i++)
            #pragma unroll
            for (int j = 0; j < 4; j++)
                #pragma unroll
                for (int e = 0; e < 4; e++) acc[i][j][e] = 0.0f;

        float ssq[8];
        #pragma unroll
        for (int q = 0; q < 8; q++) ssq[q] = 0.0f;

        #pragma unroll 1
        for (int ck = 0; ck < 8; ck++) {
            BAR_G(barid);   // group's stage (ck&1) fully consumed

            // STS vreg (chunk ck) -> stage, accumulate ssq
            unsigned bst = sbBg + (ck & 1) * G_STAGE;
            #pragma unroll
            for (int q = 0; q < 8; q++) {
                float4 v = vreg[q];
                ssq[q] += v.x*v.x + v.y*v.y + v.z*v.z + v.w*v.w;
                int row = rb + q * 8;
                *(uint2*)(smem + (bst - sbA) + row * BSTRIDE_B + seg * 8) = cvt_bf16x4(v);
            }

            if (ck == 7) {
                // reduce ssq across 16 seg-lanes, publish group row norms
                #pragma unroll
                for (int q = 0; q < 8; q++) {
                    float s = ssq[q];
                    s += __shfl_xor_sync(0xffffffffu, s, 1);
                    s += __shfl_xor_sync(0xffffffffu, s, 2);
                    s += __shfl_xor_sync(0xffffffffu, s, 4);
                    s += __shfl_xor_sync(0xffffffffu, s, 8);
                    if (seg == 0) sRssG[rb + q * 8] = s;
                }
            } else {
                // prefetch chunk ck+1 (latency hidden by MMA below)
                #pragma unroll
                for (int q = 0; q < 8; q++) {
                    int rg = nt * TILE_N + g * 64 + rb + q * 8;
                    vreg[q] = (rg < CDIM) ? wsrc[(size_t)rg * 128 + (ck + 1) * 16 + seg]
                                          : make_float4(0.f, 0.f, 0.f, 0.f);
                }
            }
            BAR_G(barid);   // stage ready (and sRss visible after ck=7)

            // ---- MMA over group stage (ck&1): 4 k16 steps ----
            unsigned bB = sbBg + (ck & 1) * G_STAGE;
            #pragma unroll
            for (int k16 = 0; k16 < 4; k16++) {
                unsigned a[4][4];
                #pragma unroll
                for (int i = 0; i < 4; i++) {
                    int r   = wm * 64 + i * 16 + (lane & 15);
                    int col = k16 * 16 + ((lane >> 4) << 3);
                    unsigned addr = sbA + r * ASTRIDE_B + col * 2;
                    asm volatile("ldmatrix.sync.aligned.m8n8.x4.shared.b16 {%0,%1,%2,%3}, [%4];"
                                 : "=r"(a[i][0]), "=r"(a[i][1]), "=r"(a[i][2]), "=r"(a[i][3])
                                 : "r"(addr));
                }
                unsigned bfr[4][2];
                #pragma unroll
                for (int j2 = 0; j2 < 2; j2++) {
                    int nrow = wn * 32 + j2 * 16 + (lane & 7) + ((lane >> 4) << 3);
                    int col  = k16 * 16 + (((lane >> 3) & 1) << 3);
                    unsigned addr = bB + nrow * BSTRIDE_B + col * 2;
                    unsigned r0, r1, r2, r3;
                    asm volatile("ldmatrix.sync.aligned.m8n8.x4.shared.b16 {%0,%1,%2,%3}, [%4];"
                                 : "=r"(r0), "=r"(r1), "=r"(r2), "=r"(r3) : "r"(addr));
                    bfr[j2 * 2 + 0][0] = r0; bfr[j2 * 2 + 0][1] = r1;
                    bfr[j2 * 2 + 1][0] = r2; bfr[j2 * 2 + 1][1] = r3;
                }
                #pragma unroll
                for (int i = 0; i < 4; i++)
                    #pragma unroll
                    for (int j = 0; j < 4; j++)
                        asm volatile(
                            "mma.sync.aligned.m16n8k16.row.col.f32.bf16.bf16.f32 "
                            "{%0,%1,%2,%3},{%4,%5,%6,%7},{%8,%9},{%0,%1,%2,%3};"
                            : "+f"(acc[i][j][0]), "+f"(acc[i][j][1]),
                              "+f"(acc[i][j][2]), "+f"(acc[i][j][3])
                            : "r"(a[i][0]), "r"(a[i][1]), "r"(a[i][2]), "r"(a[i][3]),
                              "r"(bfr[j][0]), "r"(bfr[j][1]));
            }
        }

        // prefetch chunk 0 of next tile (overlaps epilogue)
        if (nt + GRIDX < NT) {
            #pragma unroll
            for (int q = 0; q < 8; q++) {
                int rg = (nt + GRIDX) * TILE_N + g * 64 + rb + q * 8;
                vreg[q] = (rg < CDIM) ? wsrc[(size_t)rg * 128 + seg]
                                      : make_float4(0.f, 0.f, 0.f, 0.f);
            }
        }

        // ---- per-warp epilogue: z = acc * SCALE * rsqrt(||w||^2) ----
        int n0 = nt * TILE_N + g * 64;
        float rn[8];
        #pragma unroll
        for (int j = 0; j < 4; j++)
            #pragma unroll
            for (int e2 = 0; e2 < 2; e2++) {
                int tc = wn * 32 + j * 8 + t4 * 2 + e2;
                rn[j * 2 + e2] = rsqrtf(fmaxf(sRssG[tc], 1e-30f)) * SCALE_F;
            }

        #pragma unroll
        for (int i = 0; i < 4; i++) {
            #pragma unroll
            for (int h = 0; h < 2; h++) {
                float m = -INFINITY;
                float z[8];
                #pragma unroll
                for (int j = 0; j < 4; j++) {
                    #pragma unroll
                    for (int e2 = 0; e2 < 2; e2++) {
                        int gc = n0 + wn * 32 + j * 8 + t4 * 2 + e2;
                        float v = rn[j * 2 + e2] * acc[i][j][h * 2 + e2];
                        z[j * 2 + e2] = (gc < CDIM) ? v : -INFINITY;
                        m = fmaxf(m, z[j * 2 + e2]);
                    }
                }
                m = fmaxf(m, __shfl_xor_sync(0xffffffffu, m, 1));
                m = fmaxf(m, __shfl_xor_sync(0xffffffffu, m, 2));
                float s = 0.0f;
                if (m > -1e37f) {
                    #pragma unroll
                    for (int j8 = 0; j8 < 8; j8++) s += __expf(z[j8] - m);
                }
                s += __shfl_xor_sync(0xffffffffu, s, 1);
                s += __shfl_xor_sync(0xffffffffu, s, 2);
                if (t4 == 0) {
                    int r = m0 + wm * 64 + i * 16 + h * 8 + g4;
                    size_t idx = (size_t)r * NPART + nt * 4 + g * 2 + wn;
                    g_pm[idx] = fmaxf(m, -3.0e38f);   // finite sentinel
                    g_ps[idx] = s;
                }
            }
        }
    }
}

// ---------------- logsumexp merge + margin + NLL ----------------
__global__ void __launch_bounds__(256) reduce_kernel() {
    int b = blockIdx.x, tid = threadIdx.x;
    float M = -INFINITY, S = 0.0f;
    for (int i = tid; i < NPART; i += 256) {
        float m = g_pm[(size_t)b * NPART + i];
        float s = g_ps[(size_t)b * NPART + i];
        if (m > M) { S = S * __expf(M - m) + s; M = m; }
        else       { S += s * __expf(m - M); }
    }
    __shared__ float sm[256], ss[256];
    sm[tid] = M; ss[tid] = S;
    __syncthreads();
    for (int o = 128; o; o >>= 1) {
        if (tid < o) {
            float m2 = sm[tid + o], s2 = ss[tid + o];
            float m1 = sm[tid],     s1 = ss[tid];
            float mn = fmaxf(m1, m2);
            sm[tid] = mn;
            ss[tid] = s1 * __expf(m1 - mn) + s2 * __expf(m2 - mn);
        }
        __syncthreads();
    }
    if (tid == 0) {
        float Mf = sm[0], Sf = ss[0];
        float zg = SCALE_F * g_cosgt[b];
        float zm = zg - SCALE_F * MARGIN_F;
        Sf = Sf - expf(zg - Mf) + expf(zm - Mf);
        float lse = Mf + logf(Sf);
        g_nll[b] = lse - zm;
    }
}

__global__ void __launch_bounds__(512) mean_kernel(float* __restrict__ out) {
    __shared__ float sm[512];
    int t = threadIdx.x;
    sm[t] = g_nll[t];
    __syncthreads();
    for (int o = 256; o; o >>= 1) {
        if (t < o) sm[t] += sm[t + o];
        __syncthreads();
    }
    if (t == 0) out[0] = sm[0] * (1.0f / (float)BDIM);
}

// ---------------- launch ----------------
extern "C" void kernel_launch(void* const* d_in, const int* in_sizes, int n_in,
                              void* d_out, int out_size) {
    const float* x  = (const float*)d_in[0];
    const void*  gt = d_in[1];
    const float* wt = (const float*)d_in[2];
    float* out = (float*)d_out;

    static int smem_set = 0;
    if (!smem_set) {
        cudaFuncSetAttribute(gemm_softmax_kernel,
                             cudaFuncAttributeMaxDynamicSharedMemorySize, SMEM_DYN);
        smem_set = 1;
    }

    detect_gt_kernel<<<1, 512>>>((const int*)gt);
    norm_x_kernel<<<BDIM, 128>>>(x);
    cosgt_kernel<<<BDIM, 128>>>(gt, wt);
    gemm_softmax_kernel<<<dim3(GRIDX, 4), 256, SMEM_DYN>>>(wt);
    reduce_kernel<<<BDIM, 256>>>();
    mean_kernel<<<1, 512>>>(out);
}